// round 1
// baseline (speedup 1.0000x reference)
#include <cuda_runtime.h>

#define H 512
#define W 512
#define PLANE (H * W)          // 262144 = 2^18
#define NPLANES 64             // 32 pred planes + 32 true planes (channel 1 only)
#define ITERS 10
#define TILE 32

// Ping-pong scratch for the skeletonization state (allocation-free rule:
// __device__ globals). 64 MB each.
__device__ float g_bufA[(size_t)NPLANES * PLANE];
__device__ float g_bufB[(size_t)NPLANES * PLANE];
__device__ double g_acc[4];    // s_pred_cross, s_pred, s_true_cross, s_true

// One soft-skeletonize iteration, fused: erosion (3x3 min, pad +inf) ->
// dilation of erosion (3x3 max, pad -inf) -> contour -> relu update.
__global__ void __launch_bounds__(1024) iter_kernel(
    const float* __restrict__ pred, const float* __restrict__ tru, int it)
{
    __shared__ float sx[36][37];   // x tile with halo 2 (+1 col pad vs conflicts)
    __shared__ float sm[34][35];   // min-pool over halo-1 region

    const int p  = blockIdx.z;                 // plane: 0..31 pred, 32..63 true
    const int by = blockIdx.y * TILE;
    const int bx = blockIdx.x * TILE;
    const int ty = threadIdx.y, tx = threadIdx.x;
    const int tid = ty * 32 + tx;

    const float INF = __int_as_float(0x7f800000);

    const float* src;
    if (it == 0) {
        // Read channel 1 directly out of the strided (B,2,H,W) input.
        int b = p & 31;
        src = (p < 32 ? pred : tru) + (size_t)(2 * b + 1) * PLANE;
    } else {
        src = ((it & 1) ? g_bufA : g_bufB) + (size_t)p * PLANE;
    }
    float* dst = ((it & 1) ? g_bufB : g_bufA) + (size_t)p * PLANE;

    // Load 36x36 tile; outside-image = +INF (min-pool pads with +inf).
    for (int i = tid; i < 36 * 36; i += 1024) {
        int r = i / 36, c = i % 36;
        int gy = by + r - 2, gx = bx + c - 2;
        float v = INF;
        if ((unsigned)gy < H && (unsigned)gx < W)
            v = src[gy * W + gx];
        sx[r][c] = v;
    }
    __syncthreads();

    // min-pool at tile coords (r+1, c+1), r,c in [0,34). Outside-image
    // positions contribute -INF to the subsequent max-pool (maxpool pad).
    for (int i = tid; i < 34 * 34; i += 1024) {
        int r = i / 34, c = i % 34;
        int gy = by + r - 1, gx = bx + c - 1;
        float v;
        if ((unsigned)gy < H && (unsigned)gx < W) {
            float m0 = fminf(fminf(sx[r    ][c], sx[r    ][c + 1]), sx[r    ][c + 2]);
            float m1 = fminf(fminf(sx[r + 1][c], sx[r + 1][c + 1]), sx[r + 1][c + 2]);
            float m2 = fminf(fminf(sx[r + 2][c], sx[r + 2][c + 1]), sx[r + 2][c + 2]);
            v = fminf(fminf(m0, m1), m2);
        } else {
            v = -INF;
        }
        sm[r][c] = v;
    }
    __syncthreads();

    float x  = sx[ty + 2][tx + 2];
    float mp = sm[ty + 1][tx + 1];
    float d0 = fmaxf(fmaxf(sm[ty    ][tx], sm[ty    ][tx + 1]), sm[ty    ][tx + 2]);
    float d1 = fmaxf(fmaxf(sm[ty + 1][tx], sm[ty + 1][tx + 1]), sm[ty + 1][tx + 2]);
    float d2 = fmaxf(fmaxf(sm[ty + 2][tx], sm[ty + 2][tx + 1]), sm[ty + 2][tx + 2]);
    float dil = fmaxf(fmaxf(d0, d1), d2);

    float contour = fmaxf(dil - mp, 0.0f);
    float out = fmaxf(x - contour, 0.0f);
    dst[(size_t)p * 0 + (by + ty) * W + (bx + tx)] = out;  // dst already offset by plane
}

__global__ void zero_acc()
{
    if (threadIdx.x < 4) g_acc[threadIdx.x] = 0.0;
}

// Final skeletons live in g_bufB (ITERS=10: last write was it=9, odd -> bufB).
__global__ void __launch_bounds__(256) reduce_kernel(
    const float* __restrict__ pred, const float* __restrict__ tru)
{
    const size_t N = (size_t)NPLANES * PLANE;
    float a0 = 0.f, a1 = 0.f, a2 = 0.f, a3 = 0.f;

    for (size_t idx = (size_t)blockIdx.x * blockDim.x + threadIdx.x; idx < N;
         idx += (size_t)gridDim.x * blockDim.x) {
        int p = (int)(idx >> 18);          // PLANE = 2^18
        int q = (int)(idx & (PLANE - 1));
        int b = p & 31;
        float s = g_bufB[idx];
        const float* other = (p < 32) ? tru : pred;  // skel_pred*y_true ; skel_true*y_pred
        float o = other[(size_t)(2 * b + 1) * PLANE + q];
        if (p < 32) { a0 += s * o; a1 += s; }
        else        { a2 += s * o; a3 += s; }
    }

    __shared__ float red[4][256];
    red[0][threadIdx.x] = a0; red[1][threadIdx.x] = a1;
    red[2][threadIdx.x] = a2; red[3][threadIdx.x] = a3;
    __syncthreads();
    for (int s = 128; s > 0; s >>= 1) {
        if ((int)threadIdx.x < s) {
            red[0][threadIdx.x] += red[0][threadIdx.x + s];
            red[1][threadIdx.x] += red[1][threadIdx.x + s];
            red[2][threadIdx.x] += red[2][threadIdx.x + s];
            red[3][threadIdx.x] += red[3][threadIdx.x + s];
        }
        __syncthreads();
    }
    if (threadIdx.x == 0) {
        atomicAdd(&g_acc[0], (double)red[0][0]);
        atomicAdd(&g_acc[1], (double)red[1][0]);
        atomicAdd(&g_acc[2], (double)red[2][0]);
        atomicAdd(&g_acc[3], (double)red[3][0]);
    }
}

__global__ void finalize_kernel(float* out)
{
    const double SMOOTH = 1.0;
    double tprec = (g_acc[0] + SMOOTH) / (g_acc[1] + SMOOTH);
    double tsens = (g_acc[2] + SMOOTH) / (g_acc[3] + SMOOTH);
    out[0] = (float)(1.0 - 2.0 * (tprec * tsens) / (tprec + tsens));
}

extern "C" void kernel_launch(void* const* d_in, const int* in_sizes, int n_in,
                              void* d_out, int out_size)
{
    const float* pred = (const float*)d_in[0];
    const float* tru  = (const float*)d_in[1];

    dim3 grid(W / TILE, H / TILE, NPLANES);
    dim3 block(32, 32, 1);
    for (int it = 0; it < ITERS; ++it)
        iter_kernel<<<grid, block>>>(pred, tru, it);

    zero_acc<<<1, 32>>>();
    reduce_kernel<<<512, 256>>>(pred, tru);
    finalize_kernel<<<1, 1>>>((float*)d_out);
}

// round 2
// speedup vs baseline: 3.2032x; 3.2032x over previous
#include <cuda_runtime.h>

#define H 512
#define W 512
#define PLANE (H * W)          // 2^18
#define NPLANES 64             // 32 pred planes + 32 true planes (channel 1)
#define ITERS 10
#define RB 32                  // output rows per warp band
#define BANDS (H / RB)         // 16
#define STRIPS 4               // 128 cols per warp strip
#define KITER (RB + 4)         // 36 pipeline iterations (multiple of 4)

__device__ float g_bufA[(size_t)NPLANES * PLANE];
__device__ float g_bufB[(size_t)NPLANES * PLANE];
__device__ double g_acc[4];    // cross_pred, sum_pred, cross_true, sum_true

__device__ __forceinline__ float min3f(float a, float b, float c) { return fminf(fminf(a, b), c); }
__device__ __forceinline__ float max3f(float a, float b, float c) { return fmaxf(fmaxf(a, b), c); }

// One soft-skeletonize iteration. Warp-private separable stencil pipeline:
//   hmin (horizontal 3-min, shuffles) -> m = vmin3 (rolling regs)
//   hmax (horizontal 3-max, shuffles) -> dil = vmax3 (rolling regs)
//   out = relu(x - relu(dil - m))
// Min-pool pads +inf outside image; max-pool stage sees -inf for OOB m rows/cols.
template <bool FINAL>
__global__ void __launch_bounds__(128) iter_kernel(
    const float* __restrict__ pred, const float* __restrict__ tru, int it)
{
    const float PINF = __int_as_float(0x7f800000);
    const float NINF = __int_as_float(0xff800000);

    const int lane  = threadIdx.x & 31;
    const int gw    = blockIdx.x * 4 + (threadIdx.x >> 5);
    const int strip = gw & (STRIPS - 1);
    const int band  = (gw >> 2) & (BANDS - 1);
    const int p     = gw >> 6;               // plane 0..63
    const int rbase = band * RB;
    const int cb    = strip * 128 + lane * 4;

    const int b = p & 31;
    const float* chan = (p < 32 ? pred : tru) + (size_t)(2 * b + 1) * PLANE;
    const float* src  = (it == 0) ? chan
                      : (((it & 1) ? g_bufA : g_bufB) + (size_t)p * PLANE);
    float* dst = ((it & 1) ? g_bufB : g_bufA) + (size_t)p * PLANE;
    const float* oth = (p < 32 ? tru : pred) + (size_t)(2 * b + 1) * PLANE;

    const bool isL = (lane == 0), isR = (lane == 31);
    const bool eOK = isL ? (strip > 0) : (isR ? (strip < STRIPS - 1) : false);

    // Register rings (all static-indexed via unroll-by-4)
    float4 xr[4];          // raw x rows (load slot = (k+2)&3, use slot = k&3)
    float  e0r[4], e1r[4]; // warp-edge extra columns (lanes 0/31 only)
    float4 hr[4];          // hmin rows
    float  hEr[4];         // hmin extra column
    float4 mr[2];          // minpool rows (center ring)
    float4 Hr[4];          // hmax rows
    float4 xc[2];          // x center ring
    float  accC = 0.f, accS = 0.f;

    auto loadrow = [&](int r, int j) {
        float4 x;
        float e0 = PINF, e1 = PINF;
        if ((unsigned)r < H) {
            const float* row = src + (size_t)r * W;
            x = *reinterpret_cast<const float4*>(row + cb);
            if (eOK) {
                if (isL) { e0 = row[cb - 1]; e1 = row[cb - 2]; }
                else     { e0 = row[cb + 4]; e1 = row[cb + 5]; }
            }
        } else {
            x = make_float4(PINF, PINF, PINF, PINF);
        }
        xr[j] = x; e0r[j] = e0; e1r[j] = e1;
    };

    loadrow(rbase - 2, 0);
    loadrow(rbase - 1, 1);

    for (int kk = 0; kk < KITER; kk += 4) {
#pragma unroll
        for (int u = 0; u < 4; ++u) {
            const int k   = kk + u;
            const int j   = u;
            const int jm1 = (u + 3) & 3;
            const int jm2 = (u + 2) & 3;
            const int t   = rbase - 2 + k;

            // prefetch row t+2 (depth-2)
            if (k < KITER - 2) loadrow(t + 2, (u + 2) & 3);

            // prefetch other-channel row for FINAL accumulation
            float4 ov;
            const int ro = t - 2;
            if (FINAL && k >= 4)
                ov = *reinterpret_cast<const float4*>(oth + (size_t)ro * W + cb);

            // hmin of row t
            const float4 x  = xr[j];
            const float  e0 = e0r[j];
            float left  = __shfl_up_sync(0xffffffffu, x.w, 1);
            float right = __shfl_down_sync(0xffffffffu, x.x, 1);
            if (isL) left  = e0;
            if (isR) right = e0;
            float4 h;
            h.x = min3f(left, x.x, x.y);
            h.y = min3f(x.x,  x.y, x.z);
            h.z = min3f(x.y,  x.z, x.w);
            h.w = min3f(x.z,  x.w, right);
            hr[j]  = h;
            hEr[j] = min3f(e0, e1r[j], isL ? x.x : x.w);

            // minpool row t-1 (vmin3 of hmin); OOB rows => -inf for max stage
            const bool rv = ((unsigned)(t - 1) < H);
            float4 m;
            m.x = min3f(hr[j].x, hr[jm1].x, hr[jm2].x);
            m.y = min3f(hr[j].y, hr[jm1].y, hr[jm2].y);
            m.z = min3f(hr[j].z, hr[jm1].z, hr[jm2].z);
            m.w = min3f(hr[j].w, hr[jm1].w, hr[jm2].w);
            if (!rv) m = make_float4(NINF, NINF, NINF, NINF);
            const float mE = (rv && eOK) ? min3f(hEr[j], hEr[jm1], hEr[jm2]) : NINF;

            // hmax of minpool row t-1
            float lm = __shfl_up_sync(0xffffffffu, m.w, 1);
            float rm = __shfl_down_sync(0xffffffffu, m.x, 1);
            if (isL) lm = mE;
            if (isR) rm = mE;
            float4 Hh;
            Hh.x = max3f(lm,  m.x, m.y);
            Hh.y = max3f(m.x, m.y, m.z);
            Hh.z = max3f(m.y, m.z, m.w);
            Hh.w = max3f(m.z, m.w, rm);
            Hr[j] = Hh;   // slot j holds hmax(row t-1)

            // output row t-2
            if (k >= 4) {
                float4 dil;
                dil.x = max3f(Hr[j].x, Hr[jm1].x, Hr[jm2].x);
                dil.y = max3f(Hr[j].y, Hr[jm1].y, Hr[jm2].y);
                dil.z = max3f(Hr[j].z, Hr[jm1].z, Hr[jm2].z);
                dil.w = max3f(Hr[j].w, Hr[jm1].w, Hr[jm2].w);
                const float4 xcen = xc[u & 1];        // x_{t-2}
                const float4 mc   = mr[(u + 1) & 1];  // m_{t-2}
                float4 o;
                o.x = fmaxf(xcen.x - fmaxf(dil.x - mc.x, 0.f), 0.f);
                o.y = fmaxf(xcen.y - fmaxf(dil.y - mc.y, 0.f), 0.f);
                o.z = fmaxf(xcen.z - fmaxf(dil.z - mc.z, 0.f), 0.f);
                o.w = fmaxf(xcen.w - fmaxf(dil.w - mc.w, 0.f), 0.f);
                if (FINAL) {
                    accC += o.x * ov.x + o.y * ov.y + o.z * ov.z + o.w * ov.w;
                    accS += (o.x + o.y) + (o.z + o.w);
                } else {
                    *reinterpret_cast<float4*>(dst + (size_t)ro * W + cb) = o;
                }
            }

            // commit rings (reads of these slots happened above)
            xc[u & 1] = x;
            mr[u & 1] = m;
        }
    }

    if (FINAL) {
#pragma unroll
        for (int s = 16; s; s >>= 1) {
            accC += __shfl_xor_sync(0xffffffffu, accC, s);
            accS += __shfl_xor_sync(0xffffffffu, accS, s);
        }
        __shared__ float sC[4], sS[4];
        const int w = threadIdx.x >> 5;
        if (lane == 0) { sC[w] = accC; sS[w] = accS; }
        __syncthreads();
        if (threadIdx.x == 0) {
            double c = (double)sC[0] + sC[1] + sC[2] + sC[3];
            double s = (double)sS[0] + sS[1] + sS[2] + sS[3];
            const int base = (p < 32) ? 0 : 2;
            atomicAdd(&g_acc[base],     c);
            atomicAdd(&g_acc[base + 1], s);
        }
    }
}

__global__ void zero_acc()
{
    if (threadIdx.x < 4) g_acc[threadIdx.x] = 0.0;
}

__global__ void finalize_kernel(float* out)
{
    const double SMOOTH = 1.0;
    double tprec = (g_acc[0] + SMOOTH) / (g_acc[1] + SMOOTH);
    double tsens = (g_acc[2] + SMOOTH) / (g_acc[3] + SMOOTH);
    out[0] = (float)(1.0 - 2.0 * (tprec * tsens) / (tprec + tsens));
}

extern "C" void kernel_launch(void* const* d_in, const int* in_sizes, int n_in,
                              void* d_out, int out_size)
{
    const float* pred = (const float*)d_in[0];
    const float* tru  = (const float*)d_in[1];

    const int nblocks = NPLANES * BANDS * STRIPS / 4;  // 1024 blocks, 128 thr
    zero_acc<<<1, 32>>>();
    for (int it = 0; it < ITERS - 1; ++it)
        iter_kernel<false><<<nblocks, 128>>>(pred, tru, it);
    iter_kernel<true><<<nblocks, 128>>>(pred, tru, ITERS - 1);
    finalize_kernel<<<1, 1>>>((float*)d_out);
}

// round 3
// speedup vs baseline: 8.9984x; 2.8092x over previous
#include <cuda_runtime.h>
#include <cuda_fp16.h>

typedef unsigned int u32;

#define H 512
#define W 512
#define PLANE (H * W)
#define NPLANES 64          // 32 pred + 32 true planes (channel 1 only)
#define RB 16               // output rows per warp
#define BANDS (H / RB)      // 32
#define STRIPS 2            // 256 cols per warp (8 cols/lane)
#define KSTEPS (RB + 4)     // 20 pipeline steps
#define NBLOCKS (NPLANES * BANDS * STRIPS / 4)   // 1024 blocks of 128 thr

#define PINF2 0x7C007C00u
#define NINF2 0xFC00FC00u

__device__ __half g_bufA[(size_t)NPLANES * PLANE];   // 32 MB
__device__ __half g_bufB[(size_t)NPLANES * PLANE];   // 32 MB
__device__ double g_acc[4];  // cross_pred, sum_pred, cross_true, sum_true

__device__ __forceinline__ u32 h2min(u32 a, u32 b) {
    __half2 r = __hmin2(*reinterpret_cast<__half2*>(&a),
                        *reinterpret_cast<__half2*>(&b));
    return *reinterpret_cast<u32*>(&r);
}
__device__ __forceinline__ u32 h2max(u32 a, u32 b) {
    __half2 r = __hmax2(*reinterpret_cast<__half2*>(&a),
                        *reinterpret_cast<__half2*>(&b));
    return *reinterpret_cast<u32*>(&r);
}
__device__ __forceinline__ u32 h2sub(u32 a, u32 b) {
    __half2 r = __hsub2(*reinterpret_cast<__half2*>(&a),
                        *reinterpret_cast<__half2*>(&b));
    return *reinterpret_cast<u32*>(&r);
}
__device__ __forceinline__ u32 pk(float lo, float hi) {
    __half2 r = __floats2half2_rn(lo, hi);
    return *reinterpret_cast<u32*>(&r);
}
__device__ __forceinline__ float2 up(u32 v) {
    return __half22float2(*reinterpret_cast<__half2*>(&v));
}

// One soft-skeletonize iteration, vertical-first separable pipeline in regs.
// MODE 0: fp32 strided input -> half state.  MODE 1: half -> half.
// MODE 2: half -> fused reduction (no store).
template <int MODE>
__global__ void __launch_bounds__(128) skel_kernel(
    const float* __restrict__ pred, const float* __restrict__ tru, int it)
{
    const int lane  = threadIdx.x & 31;
    const int gw    = blockIdx.x * 4 + (threadIdx.x >> 5);
    const int strip = gw & 1;
    const int band  = (gw >> 1) & (BANDS - 1);
    const int p     = gw >> 6;
    const int rbase = band * RB;
    const int cb    = strip * 256 + lane * 8;
    const int b     = p & 31;

    const float* chan = (p < 32 ? pred : tru) + (size_t)(2 * b + 1) * PLANE;
    const float* oth  = (p < 32 ? tru : pred) + (size_t)(2 * b + 1) * PLANE;
    const __half* srcH = ((it & 1) ? g_bufA : g_bufB) + (size_t)p * PLANE;
    __half*       dstH = ((it & 1) ? g_bufB : g_bufA) + (size_t)p * PLANE;

    const bool edgeL = (lane == 0  && strip == 1);  // halo at cols 254..255
    const bool edgeR = (lane == 31 && strip == 0);  // halo at cols 256..257

    u32 xr[4][4];    // x rows ring   (slot = (r - rbase + 2) & 3)
    u32 xer[4];      // edge halo half2 ring
    u32 mr[4][4];    // min-pool rows ring (slot = k & 3)
    u32 mer[4];      // edge min-pool scalar ring (lo half)
    float accC = 0.f, accS = 0.f;

#pragma unroll
    for (int s = 2; s < 4; ++s) {
        xr[s][0] = xr[s][1] = xr[s][2] = xr[s][3] = PINF2;
        xer[s] = PINF2;
    }

    auto loadrow = [&](int r, int s) {
        u32 a0 = PINF2, a1 = PINF2, a2 = PINF2, a3 = PINF2, ae = PINF2;
        if ((unsigned)r < H) {
            if (MODE == 0) {
                const float* row = chan + (size_t)r * W + cb;
                float4 f0 = *reinterpret_cast<const float4*>(row);
                float4 f1 = *reinterpret_cast<const float4*>(row + 4);
                a0 = pk(f0.x, f0.y); a1 = pk(f0.z, f0.w);
                a2 = pk(f1.x, f1.y); a3 = pk(f1.z, f1.w);
                if (edgeL) {
                    float2 e = *reinterpret_cast<const float2*>(row - 2);
                    ae = pk(e.x, e.y);
                } else if (edgeR) {
                    float2 e = *reinterpret_cast<const float2*>(row + 8);
                    ae = pk(e.x, e.y);
                }
            } else {
                const __half* row = srcH + (size_t)r * W + cb;
                uint4 v = *reinterpret_cast<const uint4*>(row);
                a0 = v.x; a1 = v.y; a2 = v.z; a3 = v.w;
                if (edgeL)      ae = *reinterpret_cast<const u32*>(row - 2);
                else if (edgeR) ae = *reinterpret_cast<const u32*>(row + 8);
            }
        }
        xr[s][0] = a0; xr[s][1] = a1; xr[s][2] = a2; xr[s][3] = a3;
        xer[s] = ae;
    };

    loadrow(rbase - 2, 0);

#pragma unroll 1
    for (int kk = 0; kk < KSTEPS; kk += 4) {
        const bool OUT = (kk >= 4);
#pragma unroll
        for (int u = 0; u < 4; ++u) {
            const int k  = kk + u;
            const int s0 = (u + 2) & 3;   // (k-2)&3
            const int s1 = (u + 3) & 3;   // (k-1)&3
            const int s2 = u;             //  k   &3
            const int s3 = (u + 1) & 3;   // (k+1)&3

            loadrow(rbase - 1 + k, s3);   // prefetch (used next step)

            // ---- min-pool row rm = rbase-3+k  (x rows rm-1..rm+1 = s0,s1,s2)
            const int rm = rbase - 3 + k;
            u32 v1[4];
#pragma unroll
            for (int i = 0; i < 4; ++i)
                v1[i] = h2min(h2min(xr[s0][i], xr[s1][i]), xr[s2][i]);
            u32 v1e = h2min(h2min(xer[s0], xer[s1]), xer[s2]);

            u32 prevU = __shfl_up_sync(0xffffffffu, v1[3], 1);
            u32 nxtU  = __shfl_down_sync(0xffffffffu, v1[0], 1);
            if (lane == 0)  prevU = edgeL ? v1e : 0x7C000000u;  // hi = col-1
            if (lane == 31) nxtU  = edgeR ? v1e : 0x00007C00u;  // lo = col+8

            u32 P0 = __byte_perm(prevU, v1[0], 0x5432);
            u32 P1 = __byte_perm(v1[0], v1[1], 0x5432);
            u32 P2 = __byte_perm(v1[1], v1[2], 0x5432);
            u32 P3 = __byte_perm(v1[2], v1[3], 0x5432);
            u32 P4 = __byte_perm(v1[3], nxtU,  0x5432);

            u32 m0 = h2min(h2min(P0, v1[0]), P1);
            u32 m1 = h2min(h2min(P1, v1[1]), P2);
            u32 m2 = h2min(h2min(P2, v1[2]), P3);
            u32 m3 = h2min(h2min(P3, v1[3]), P4);

            // edge scalar min-pool (col 255 for edgeL / col 256 for edgeR)
            u32 vsw = __byte_perm(v1e, v1e, 0x1032);
            u32 me  = h2min(v1e, vsw);
            me = h2min(me, edgeL ? v1[0] : (v1[3] >> 16));

            if ((unsigned)rm >= H) {                 // maxpool pads -inf
                m0 = m1 = m2 = m3 = NINF2; me = NINF2;
            }
            mr[s2][0] = m0; mr[s2][1] = m1; mr[s2][2] = m2; mr[s2][3] = m3;
            mer[s2] = me;

            // ---- output row o = rbase-4+k  (m rows o-1..o+1 = s0,s1,s2)
            if (OUT) {
                const int o = rbase - 4 + k;
                u32 w[4];
#pragma unroll
                for (int i = 0; i < 4; ++i)
                    w[i] = h2max(h2max(mr[s0][i], mr[s1][i]), mr[s2][i]);
                u32 we = h2max(h2max(mer[s0], mer[s1]), mer[s2]);

                u32 prevM = __shfl_up_sync(0xffffffffu, w[3], 1);
                u32 nxtM  = __shfl_down_sync(0xffffffffu, w[0], 1);
                if (lane == 0)  prevM = edgeL ? (we << 16)    : 0xFC000000u;
                if (lane == 31) nxtM  = edgeR ? (we & 0xFFFFu) : 0x0000FC00u;

                u32 Q0 = __byte_perm(prevM, w[0], 0x5432);
                u32 Q1 = __byte_perm(w[0], w[1], 0x5432);
                u32 Q2 = __byte_perm(w[1], w[2], 0x5432);
                u32 Q3 = __byte_perm(w[2], w[3], 0x5432);
                u32 Q4 = __byte_perm(w[3], nxtM, 0x5432);

                u32 d0 = h2max(h2max(Q0, w[0]), Q1);
                u32 d1 = h2max(h2max(Q1, w[1]), Q2);
                u32 d2 = h2max(h2max(Q2, w[2]), Q3);
                u32 d3 = h2max(h2max(Q3, w[3]), Q4);

                // z = relu(x_o - relu(dil - m_o)); x_o = slot s0, m_o = slot s1
                u32 z0 = h2max(h2sub(xr[s0][0], h2max(h2sub(d0, mr[s1][0]), 0u)), 0u);
                u32 z1 = h2max(h2sub(xr[s0][1], h2max(h2sub(d1, mr[s1][1]), 0u)), 0u);
                u32 z2 = h2max(h2sub(xr[s0][2], h2max(h2sub(d2, mr[s1][2]), 0u)), 0u);
                u32 z3 = h2max(h2sub(xr[s0][3], h2max(h2sub(d3, mr[s1][3]), 0u)), 0u);

                if (MODE == 2) {
                    const float* orow = oth + (size_t)o * W + cb;
                    float4 f0 = *reinterpret_cast<const float4*>(orow);
                    float4 f1 = *reinterpret_cast<const float4*>(orow + 4);
                    float2 a0 = up(z0), a1 = up(z1), a2 = up(z2), a3 = up(z3);
                    accC += a0.x * f0.x + a0.y * f0.y + a1.x * f0.z + a1.y * f0.w;
                    accC += a2.x * f1.x + a2.y * f1.y + a3.x * f1.z + a3.y * f1.w;
                    accS += (a0.x + a0.y) + (a1.x + a1.y)
                          + (a2.x + a2.y) + (a3.x + a3.y);
                } else {
                    uint4 st; st.x = z0; st.y = z1; st.z = z2; st.w = z3;
                    *reinterpret_cast<uint4*>(dstH + (size_t)o * W + cb) = st;
                }
            }
        }
    }

    if (MODE == 2) {
#pragma unroll
        for (int s = 16; s; s >>= 1) {
            accC += __shfl_xor_sync(0xffffffffu, accC, s);
            accS += __shfl_xor_sync(0xffffffffu, accS, s);
        }
        __shared__ float sC[4], sS[4];
        const int wi = threadIdx.x >> 5;
        if (lane == 0) { sC[wi] = accC; sS[wi] = accS; }
        __syncthreads();
        if (threadIdx.x == 0) {
            double c = (double)sC[0] + sC[1] + sC[2] + sC[3];
            double s = (double)sS[0] + sS[1] + sS[2] + sS[3];
            const int base = (p < 32) ? 0 : 2;   // p constant within block
            atomicAdd(&g_acc[base],     c);
            atomicAdd(&g_acc[base + 1], s);
        }
    }
}

__global__ void zero_acc()
{
    if (threadIdx.x < 4) g_acc[threadIdx.x] = 0.0;
}

__global__ void finalize_kernel(float* out)
{
    const double SMOOTH = 1.0;
    double tprec = (g_acc[0] + SMOOTH) / (g_acc[1] + SMOOTH);
    double tsens = (g_acc[2] + SMOOTH) / (g_acc[3] + SMOOTH);
    out[0] = (float)(1.0 - 2.0 * (tprec * tsens) / (tprec + tsens));
}

extern "C" void kernel_launch(void* const* d_in, const int* in_sizes, int n_in,
                              void* d_out, int out_size)
{
    const float* pred = (const float*)d_in[0];
    const float* tru  = (const float*)d_in[1];

    zero_acc<<<1, 32>>>();
    skel_kernel<0><<<NBLOCKS, 128>>>(pred, tru, 0);
    for (int it = 1; it < 9; ++it)
        skel_kernel<1><<<NBLOCKS, 128>>>(pred, tru, it);
    skel_kernel<2><<<NBLOCKS, 128>>>(pred, tru, 9);
    finalize_kernel<<<1, 1>>>((float*)d_out);
}